// round 5
// baseline (speedup 1.0000x reference)
#include <cuda_runtime.h>
#include <cuda_fp16.h>
#include <cstdint>

// ============================================================================
// C[8192,1024] = A[8192,4096] @ B[1024,4096]^T   (fp32 in/out)
//
// Base sm_103 (no tcgen05). fp16 mma.sync.m16n8k16, at the legacy HMMA rate
// cap (R3/R4 evidence). R5: A fp32->fp16 conversion fused INTO the GEMM
// mainloop (panel kt+2 converted while computing kt), cross-CTA octet
// handshake via device flags. Removes the 31.6us serial cvt_A pass.
// ============================================================================

static constexpr int M_TOTAL = 8192;
static constexpr int K_DIM   = 4096;
static constexpr int N_TOTAL = 1024;

static constexpr int BM = 128;
static constexpr int BN = 128;
static constexpr int BK = 64;          // 64 fp16 = 128 B per smem row = one panel
static constexpr int STAGES = 3;
static constexpr int NK = K_DIM / BK;  // 64 panels

static constexpr int MT = M_TOTAL / BM;   // 64 m-tiles
static constexpr int NT = N_TOTAL / BN;   // 8 n-tiles (octet size)

static constexpr int TILE_BYTES  = BM * BK * 2;          // 16384
static constexpr int STAGE_BYTES = 2 * TILE_BYTES;       // 32768
static constexpr int SMEM_TOTAL  = STAGES * STAGE_BYTES; // 98304 -> 2 CTAs/SM

// --------------------------------------------------------------------------
// Static scratch
// --------------------------------------------------------------------------
__device__ __half g_Ah[(size_t)M_TOTAL * K_DIM];
__device__ __half g_Bh[(size_t)N_TOTAL * K_DIM];
__device__ int    g_flags[MT][NK];    // arrive count (target 8) per (m-tile, panel)

// --------------------------------------------------------------------------
// Flag zeroing (graph replays must start clean)
// --------------------------------------------------------------------------
__global__ void zero_flags_kernel() {
    int i = blockIdx.x * blockDim.x + threadIdx.x;
    if (i < MT * NK) (&g_flags[0][0])[i] = 0;
}

// --------------------------------------------------------------------------
// B convert: fp32 -> fp16 (small: 4.5us)
// --------------------------------------------------------------------------
__global__ void __launch_bounds__(256)
cvt_kernel(const float4* __restrict__ src, uint2* __restrict__ dst, int n4) {
    int i = blockIdx.x * blockDim.x + threadIdx.x;
    if (i >= n4) return;
    float4 v = src[i];
    __half2 lo = __floats2half2_rn(v.x, v.y);
    __half2 hi = __floats2half2_rn(v.z, v.w);
    dst[i] = make_uint2(*reinterpret_cast<uint32_t*>(&lo), *reinterpret_cast<uint32_t*>(&hi));
}

// --------------------------------------------------------------------------
// PTX helpers
// --------------------------------------------------------------------------
__device__ __forceinline__ void cp_async16(uint32_t saddr, const void* gptr) {
    asm volatile("cp.async.cg.shared.global [%0], [%1], 16;"
                 :: "r"(saddr), "l"(__cvta_generic_to_global(gptr)) : "memory");
}

#define CP_COMMIT() asm volatile("cp.async.commit_group;" ::: "memory")
#define CP_WAIT(N)  asm volatile("cp.async.wait_group %0;" :: "n"(N) : "memory")

#define LDSM_X4(R, addr)                                                     \
    asm volatile("ldmatrix.sync.aligned.m8n8.x4.shared.b16 {%0,%1,%2,%3}, [%4];" \
                 : "=r"((R)[0]), "=r"((R)[1]), "=r"((R)[2]), "=r"((R)[3])    \
                 : "r"(addr))

#define MMA_F16(C, A, B0, B1)                                                \
    asm volatile("mma.sync.aligned.m16n8k16.row.col.f32.f16.f16.f32 "        \
                 "{%0,%1,%2,%3}, {%4,%5,%6,%7}, {%8,%9}, {%0,%1,%2,%3};"     \
                 : "+f"((C)[0]), "+f"((C)[1]), "+f"((C)[2]), "+f"((C)[3])    \
                 : "r"((A)[0]), "r"((A)[1]), "r"((A)[2]), "r"((A)[3]),       \
                   "r"(B0), "r"(B1))

__device__ __forceinline__ uint32_t swz(int row, int col_bytes) {
    return (uint32_t)(row * 128 + (col_bytes ^ ((row & 7) * 16)));
}

// --------------------------------------------------------------------------
// Fused convert+GEMM: CTA 128x128x64, 8 warps of 32x64, 3-stage cp.async
// --------------------------------------------------------------------------
__global__ void __launch_bounds__(256, 2)
gemm_fused_kernel(const float* __restrict__ A32, float* __restrict__ C) {
    extern __shared__ uint8_t smem[];
    const uint32_t sbase = (uint32_t)__cvta_generic_to_shared(smem);

    const int tid  = threadIdx.x;
    const int lane = tid & 31;
    const int wid  = tid >> 5;
    const int wm   = (wid & 3) * 32;
    const int wn   = (wid >> 2) * 64;

    const int bid = blockIdx.x;
    const int mt  = bid >> 3;        // octet id = m-tile
    const int nt  = bid & 7;         // member id = n-tile
    const int m0  = mt * BM;
    const int n0  = nt * BN;
    const int r0c = m0 + nt * 16;    // this CTA converts rows r0c..r0c+15

    // ---- converter: panel p (64 cols) of this CTA's 16 rows ----
    const int cv_row = r0c + (tid >> 4);
    const int cv_ci  = (tid & 15) * 4;
    auto convert_panel = [&](int p) {
        const size_t off = (size_t)cv_row * K_DIM + p * BK + cv_ci;
        const float4 v = *reinterpret_cast<const float4*>(A32 + off);
        __half2 lo = __floats2half2_rn(v.x, v.y);
        __half2 hi = __floats2half2_rn(v.z, v.w);
        *reinterpret_cast<uint2*>(&g_Ah[off]) =
            make_uint2(*reinterpret_cast<const uint32_t*>(&lo),
                       *reinterpret_cast<const uint32_t*>(&hi));
    };
    auto signal_panel = [&](int p) {      // call after __threadfence + __syncthreads
        if (tid == 0) atomicAdd(&g_flags[mt][p], 1);
    };
    auto poll_panel = [&](int p) {
        const int* f = &g_flags[mt][p];
        int v;
        for (;;) {
            asm volatile("ld.acquire.gpu.global.s32 %0, [%1];" : "=r"(v) : "l"(f));
            if (v >= 8) break;
            __nanosleep(64);
        }
    };

    // ---- stage loader ----
    auto load_stage = [&](int s, int kt) {
        const uint32_t st = sbase + s * STAGE_BYTES;
        const int kbase = kt * BK;
        #pragma unroll
        for (int i = 0; i < 4; i++) {
            const int idx = tid + i * 256;
            const int row = idx >> 3;
            const int ch  = idx & 7;
            const uint32_t soff = swz(row, ch * 16);
            cp_async16(st +              soff, &g_Ah[(size_t)(m0 + row) * K_DIM + kbase + ch * 8]);
            cp_async16(st + TILE_BYTES + soff, &g_Bh[(size_t)(n0 + row) * K_DIM + kbase + ch * 8]);
        }
    };

    // ---- ldmatrix address components ----
    int a_row[2], a_xor[2];
    #pragma unroll
    for (int m = 0; m < 2; m++) {
        const int r = wm + m * 16 + (lane & 15);
        a_row[m] = r * 128;
        a_xor[m] = (r & 7) * 16;
    }
    const int a_colb = (lane >> 4) * 16;
    int b_row[4], b_xor[4];
    #pragma unroll
    for (int p = 0; p < 4; p++) {
        const int r = wn + p * 16 + (lane & 7) + ((lane >> 4) << 3);
        b_row[p] = r * 128;
        b_xor[p] = (r & 7) * 16;
    }
    const int b_colb = ((lane >> 3) & 1) * 16;

    float acc[2][8][4];
    #pragma unroll
    for (int m = 0; m < 2; m++)
        #pragma unroll
        for (int n = 0; n < 8; n++)
            #pragma unroll
            for (int q = 0; q < 4; q++) acc[m][n][q] = 0.f;

    // ---- prologue: convert + publish panels 0,1; then 2 stages in flight ----
    convert_panel(0);
    convert_panel(1);
    __threadfence();
    __syncthreads();
    signal_panel(0);
    signal_panel(1);
    poll_panel(0);
    poll_panel(1);
    load_stage(0, 0); CP_COMMIT();
    load_stage(1, 1); CP_COMMIT();

    // ---- mainloop ----
    for (int kt = 0; kt < NK; kt++) {
        const bool has_next = (kt + 2 < NK);
        if (has_next) {
            convert_panel(kt + 2);
            __threadfence();
        }
        if (kt < NK - 1) { CP_WAIT(1); } else { CP_WAIT(0); }
        __syncthreads();   // stage kt ready; stage kt-1 consumed; fences ordered
        if (has_next) {
            signal_panel(kt + 2);
            poll_panel(kt + 2);
            load_stage((kt + 2) % STAGES, kt + 2);
            CP_COMMIT();
        }

        const uint32_t st = sbase + (kt % STAGES) * STAGE_BYTES;
        #pragma unroll
        for (int ks = 0; ks < 4; ks++) {
            const int kb = ks * 32;
            uint32_t a[2][4];
            #pragma unroll
            for (int m = 0; m < 2; m++)
                LDSM_X4(a[m], st + a_row[m] + ((kb + a_colb) ^ a_xor[m]));
            uint32_t b[4][4];
            #pragma unroll
            for (int p = 0; p < 4; p++)
                LDSM_X4(b[p], st + TILE_BYTES + b_row[p] + ((kb + b_colb) ^ b_xor[p]));
            #pragma unroll
            for (int m = 0; m < 2; m++)
                #pragma unroll
                for (int p = 0; p < 4; p++)
                    #pragma unroll
                    for (int q = 0; q < 2; q++)
                        MMA_F16(acc[m][2 * p + q], a[m], b[p][2 * q], b[p][2 * q + 1]);
        }
    }

    // ---- epilogue: direct STG.64 ----
    #pragma unroll
    for (int m = 0; m < 2; m++) {
        const int r0 = m0 + wm + m * 16 + (lane >> 2);
        #pragma unroll
        for (int n = 0; n < 8; n++) {
            const int col = n0 + wn + n * 8 + (lane & 3) * 2;
            float2* p0 = reinterpret_cast<float2*>(&C[(size_t)r0 * N_TOTAL + col]);
            float2* p1 = reinterpret_cast<float2*>(&C[(size_t)(r0 + 8) * N_TOTAL + col]);
            *p0 = make_float2(acc[m][n][0], acc[m][n][1]);
            *p1 = make_float2(acc[m][n][2], acc[m][n][3]);
        }
    }
}

// --------------------------------------------------------------------------
// Launch
// --------------------------------------------------------------------------
extern "C" void kernel_launch(void* const* d_in, const int* in_sizes, int n_in,
                              void* d_out, int out_size) {
    const float* A = (const float*)d_in[0];   // [8192, 4096]
    const float* B = (const float*)d_in[1];   // [1024, 4096]
    float* C = (float*)d_out;                 // [8192, 1024]

    __half* bH;
    cudaGetSymbolAddress((void**)&bH, g_Bh);

    zero_flags_kernel<<<(MT * NK + 255) / 256, 256>>>();

    const int nB4 = (N_TOTAL * K_DIM) / 4;
    cvt_kernel<<<(nB4 + 255) / 256, 256>>>((const float4*)B, (uint2*)bH, nB4);

    static bool attr_set = false;
    if (!attr_set) {
        cudaFuncSetAttribute(gemm_fused_kernel,
                             cudaFuncAttributeMaxDynamicSharedMemorySize, SMEM_TOTAL);
        attr_set = true;
    }
    gemm_fused_kernel<<<MT * NT, 256, SMEM_TOTAL>>>(A, C);
}

// round 6
// speedup vs baseline: 1.5795x; 1.5795x over previous
#include <cuda_runtime.h>
#include <cuda_fp16.h>
#include <cstdint>

// ============================================================================
// C[8192,1024] = A[8192,4096] @ B[1024,4096]^T   (fp32 in/out)
//
// Base sm_103 (no tcgen05). fp16 mma.sync.m16n8k16 at the legacy HMMA rate
// cap. R6: A is loaded fp32 -> converted in-register -> STS'd to the fp16
// stage INSIDE the GEMM (per-CTA, redundant across the 8 n-CTAs, L2-served),
// eliminating the 31.6us serial cvt_A pass. No cross-CTA sync (R5 lesson).
// ============================================================================

static constexpr int M_TOTAL = 8192;
static constexpr int K_DIM   = 4096;
static constexpr int N_TOTAL = 1024;

static constexpr int BM = 128;
static constexpr int BN = 128;
static constexpr int BK = 64;          // 64 fp16 = 128 B per smem row
static constexpr int STAGES = 3;
static constexpr int NK = K_DIM / BK;  // 64

static constexpr int TILE_BYTES  = BM * BK * 2;          // 16384 (fp16 tile)
static constexpr int STAGE_BYTES = 2 * TILE_BYTES;       // 32768 (A + B)
static constexpr int SMEM_TOTAL  = STAGES * STAGE_BYTES; // 98304 -> 2 CTAs/SM

// --------------------------------------------------------------------------
// Static scratch: fp16 B only (A converted in-kernel)
// --------------------------------------------------------------------------
__device__ __half g_Bh[(size_t)N_TOTAL * K_DIM];

// --------------------------------------------------------------------------
// B convert: fp32 -> fp16
// --------------------------------------------------------------------------
__global__ void __launch_bounds__(256)
cvt_kernel(const float4* __restrict__ src, uint2* __restrict__ dst, int n4) {
    int i = blockIdx.x * blockDim.x + threadIdx.x;
    if (i >= n4) return;
    float4 v = src[i];
    __half2 lo = __floats2half2_rn(v.x, v.y);
    __half2 hi = __floats2half2_rn(v.z, v.w);
    dst[i] = make_uint2(*reinterpret_cast<uint32_t*>(&lo), *reinterpret_cast<uint32_t*>(&hi));
}

// --------------------------------------------------------------------------
// PTX helpers
// --------------------------------------------------------------------------
__device__ __forceinline__ void cp_async16(uint32_t saddr, const void* gptr) {
    asm volatile("cp.async.cg.shared.global [%0], [%1], 16;"
                 :: "r"(saddr), "l"(__cvta_generic_to_global(gptr)) : "memory");
}

#define CP_COMMIT() asm volatile("cp.async.commit_group;" ::: "memory")
#define CP_WAIT(N)  asm volatile("cp.async.wait_group %0;" :: "n"(N) : "memory")

#define LDSM_X4(R, addr)                                                     \
    asm volatile("ldmatrix.sync.aligned.m8n8.x4.shared.b16 {%0,%1,%2,%3}, [%4];" \
                 : "=r"((R)[0]), "=r"((R)[1]), "=r"((R)[2]), "=r"((R)[3])    \
                 : "r"(addr))

#define MMA_F16(C, A, B0, B1)                                                \
    asm volatile("mma.sync.aligned.m16n8k16.row.col.f32.f16.f16.f32 "        \
                 "{%0,%1,%2,%3}, {%4,%5,%6,%7}, {%8,%9}, {%0,%1,%2,%3};"     \
                 : "+f"((C)[0]), "+f"((C)[1]), "+f"((C)[2]), "+f"((C)[3])    \
                 : "r"((A)[0]), "r"((A)[1]), "r"((A)[2]), "r"((A)[3]),       \
                   "r"(B0), "r"(B1))

__device__ __forceinline__ uint32_t swz(int row, int col_bytes) {
    return (uint32_t)(row * 128 + (col_bytes ^ ((row & 7) * 16)));
}

__device__ __forceinline__ uint32_t pack_h2(float x, float y) {
    __half2 h = __floats2half2_rn(x, y);
    return *reinterpret_cast<uint32_t*>(&h);
}

// --------------------------------------------------------------------------
// GEMM: CTA 128x128x64, 8 warps of 32x64, 3-stage pipeline, 2 CTAs/SM.
// A path: LDG fp32 (L2-shared across octet) -> cvt -> STS fp16.
// B path: cp.async from pre-converted g_Bh.
// --------------------------------------------------------------------------
__global__ void __launch_bounds__(256, 2)
gemm_f16_kernel(const float* __restrict__ A32, float* __restrict__ C) {
    extern __shared__ uint8_t smem[];
    const uint32_t sbase = (uint32_t)__cvta_generic_to_shared(smem);

    const int tid  = threadIdx.x;
    const int lane = tid & 31;
    const int wid  = tid >> 5;
    const int wm   = (wid & 3) * 32;
    const int wn   = (wid >> 2) * 64;

    // n-fastest bid order: 8 consecutive CTAs share one m-tile (A L2 reuse)
    const int mt = blockIdx.x >> 3;
    const int nt = blockIdx.x & 7;
    const int m0 = mt * BM;
    const int n0 = nt * BN;

    // ---- A chunk geometry: 1024 chunks of 16B fp16 (= 32B fp32 source) ----
    // chunk idx = tid + i*256 (i<4): row = idx>>3, ch = idx&7 (8 chunks/row)
    int a_rowi[4], a_chi[4];
    uint32_t a_soff[4];
    #pragma unroll
    for (int i = 0; i < 4; i++) {
        const int idx = tid + i * 256;
        a_rowi[i] = idx >> 3;
        a_chi[i]  = idx & 7;
        a_soff[i] = swz(a_rowi[i], a_chi[i] * 16);
    }

    auto lda_batch = [&](int i, int kt, float4& v0, float4& v1) {
        const float* p = A32 + (size_t)(m0 + a_rowi[i]) * K_DIM + kt * BK + a_chi[i] * 8;
        v0 = __ldg(reinterpret_cast<const float4*>(p));
        v1 = __ldg(reinterpret_cast<const float4*>(p) + 1);
    };
    auto sta_batch = [&](int i, uint32_t st, const float4& v0, const float4& v1) {
        uint4 h;
        h.x = pack_h2(v0.x, v0.y); h.y = pack_h2(v0.z, v0.w);
        h.z = pack_h2(v1.x, v1.y); h.w = pack_h2(v1.z, v1.w);
        *reinterpret_cast<uint4*>(smem + (st - sbase) + a_soff[i]) = h;
    };

    auto load_b = [&](int s, int kt) {
        const uint32_t st = sbase + s * STAGE_BYTES + TILE_BYTES;
        #pragma unroll
        for (int i = 0; i < 4; i++) {
            const int idx = tid + i * 256;
            const int row = idx >> 3;
            const int ch  = idx & 7;
            cp_async16(st + swz(row, ch * 16),
                       &g_Bh[(size_t)(n0 + row) * K_DIM + kt * BK + ch * 8]);
        }
    };

    // ---- ldmatrix address components ----
    int a_row[2], a_xor[2];
    #pragma unroll
    for (int m = 0; m < 2; m++) {
        const int r = wm + m * 16 + (lane & 15);
        a_row[m] = r * 128;
        a_xor[m] = (r & 7) * 16;
    }
    const int a_colb = (lane >> 4) * 16;
    int b_row[4], b_xor[4];
    #pragma unroll
    for (int p = 0; p < 4; p++) {
        const int r = wn + p * 16 + (lane & 7) + ((lane >> 4) << 3);
        b_row[p] = r * 128;
        b_xor[p] = (r & 7) * 16;
    }
    const int b_colb = ((lane >> 3) & 1) * 16;

    float acc[2][8][4];
    #pragma unroll
    for (int m = 0; m < 2; m++)
        #pragma unroll
        for (int n = 0; n < 8; n++)
            #pragma unroll
            for (int q = 0; q < 4; q++) acc[m][n][q] = 0.f;

    // ---- prologue: A(0),A(1) direct LDG->cvt->STS; B(0),B(1) cp.async ----
    #pragma unroll
    for (int kt = 0; kt < 2; kt++) {
        const uint32_t st = sbase + kt * STAGE_BYTES;
        #pragma unroll
        for (int i = 0; i < 4; i++) {
            float4 v0, v1;
            lda_batch(i, kt, v0, v1);
            sta_batch(i, st, v0, v1);
        }
        load_b(kt, kt);
        CP_COMMIT();
    }

    // ---- mainloop ----
    for (int kt = 0; kt < NK; kt++) {
        if (kt < NK - 1) { CP_WAIT(1); } else { CP_WAIT(0); }
        __syncthreads();   // B(kt) + A(kt) STS visible; stage (kt+2)%3 freed

        const bool has_next = (kt + 2 < NK);
        const uint32_t stn = sbase + ((kt + 2) % STAGES) * STAGE_BYTES;
        float4 p0a, p0b, p1a, p1b;
        if (has_next) {
            load_b((kt + 2) % STAGES, kt + 2);
            CP_COMMIT();
            lda_batch(0, kt + 2, p0a, p0b);    // prefetch batch 1 (chunks 0,1)
            lda_batch(1, kt + 2, p1a, p1b);
        }

        const uint32_t st = sbase + (kt % STAGES) * STAGE_BYTES;

        // compute first half (ks = 0,1) while batch-1 LDGs land
        #pragma unroll
        for (int ks = 0; ks < 2; ks++) {
            const int kb = ks * 32;
            uint32_t a[2][4];
            #pragma unroll
            for (int m = 0; m < 2; m++)
                LDSM_X4(a[m], st + a_row[m] + ((kb + a_colb) ^ a_xor[m]));
            uint32_t b[4][4];
            #pragma unroll
            for (int p = 0; p < 4; p++)
                LDSM_X4(b[p], st + TILE_BYTES + b_row[p] + ((kb + b_colb) ^ b_xor[p]));
            #pragma unroll
            for (int m = 0; m < 2; m++)
                #pragma unroll
                for (int p = 0; p < 4; p++)
                    #pragma unroll
                    for (int q = 0; q < 2; q++)
                        MMA_F16(acc[m][2 * p + q], a[m], b[p][2 * q], b[p][2 * q + 1]);
        }

        if (has_next) {
            sta_batch(0, stn, p0a, p0b);       // store batch 1
            sta_batch(1, stn, p1a, p1b);
            lda_batch(2, kt + 2, p0a, p0b);    // prefetch batch 2 (chunks 2,3)
            lda_batch(3, kt + 2, p1a, p1b);
        }

        // compute second half (ks = 2,3) while batch-2 LDGs land
        #pragma unroll
        for (int ks = 2; ks < 4; ks++) {
            const int kb = ks * 32;
            uint32_t a[2][4];
            #pragma unroll
            for (int m = 0; m < 2; m++)
                LDSM_X4(a[m], st + a_row[m] + ((kb + a_colb) ^ a_xor[m]));
            uint32_t b[4][4];
            #pragma unroll
            for (int p = 0; p < 4; p++)
                LDSM_X4(b[p], st + TILE_BYTES + b_row[p] + ((kb + b_colb) ^ b_xor[p]));
            #pragma unroll
            for (int m = 0; m < 2; m++)
                #pragma unroll
                for (int p = 0; p < 4; p++)
                    #pragma unroll
                    for (int q = 0; q < 2; q++)
                        MMA_F16(acc[m][2 * p + q], a[m], b[p][2 * q], b[p][2 * q + 1]);
        }

        if (has_next) {
            sta_batch(2, stn, p0a, p0b);       // store batch 2
            sta_batch(3, stn, p1a, p1b);
        }
    }

    // ---- epilogue: direct STG.64 ----
    #pragma unroll
    for (int m = 0; m < 2; m++) {
        const int r0 = m0 + wm + m * 16 + (lane >> 2);
        #pragma unroll
        for (int n = 0; n < 8; n++) {
            const int col = n0 + wn + n * 8 + (lane & 3) * 2;
            float2* q0 = reinterpret_cast<float2*>(&C[(size_t)r0 * N_TOTAL + col]);
            float2* q1 = reinterpret_cast<float2*>(&C[(size_t)(r0 + 8) * N_TOTAL + col]);
            *q0 = make_float2(acc[m][n][0], acc[m][n][1]);
            *q1 = make_float2(acc[m][n][2], acc[m][n][3]);
        }
    }
}

// --------------------------------------------------------------------------
// Launch
// --------------------------------------------------------------------------
extern "C" void kernel_launch(void* const* d_in, const int* in_sizes, int n_in,
                              void* d_out, int out_size) {
    const float* A = (const float*)d_in[0];   // [8192, 4096]
    const float* B = (const float*)d_in[1];   // [1024, 4096]
    float* C = (float*)d_out;                 // [8192, 1024]

    __half* bH;
    cudaGetSymbolAddress((void**)&bH, g_Bh);

    const int nB4 = (N_TOTAL * K_DIM) / 4;
    cvt_kernel<<<(nB4 + 255) / 256, 256>>>((const float4*)B, (uint2*)bH, nB4);

    static bool attr_set = false;
    if (!attr_set) {
        cudaFuncSetAttribute(gemm_f16_kernel,
                             cudaFuncAttributeMaxDynamicSharedMemorySize, SMEM_TOTAL);
        attr_set = true;
    }
    const int grid = (M_TOTAL / BM) * (N_TOTAL / BN);   // 512
    gemm_f16_kernel<<<grid, 256, SMEM_TOTAL>>>(A, C);
}

// round 7
// speedup vs baseline: 1.7248x; 1.0920x over previous
#include <cuda_runtime.h>
#include <cuda_fp16.h>
#include <cstdint>

// ============================================================================
// C[8192,1024] = A[8192,4096] @ B[1024,4096]^T   (fp32 in/out)
//
// Base sm_103 (no tcgen05). fp16 mma.sync.m16n8k16 (rel_err 2.9e-4).
// R7: R3 champion structure + software-pipelined fragment loads
// (LDSM for ks+1 issued before MMAs of ks) + merged convert kernel.
// ============================================================================

static constexpr int M_TOTAL = 8192;
static constexpr int K_DIM   = 4096;
static constexpr int N_TOTAL = 1024;

static constexpr int BM = 128;
static constexpr int BN = 128;
static constexpr int BK = 64;          // 64 fp16 = 128 B per smem row
static constexpr int STAGES = 3;
static constexpr int NK = K_DIM / BK;  // 64

static constexpr int TILE_BYTES  = BM * BK * 2;          // 16384
static constexpr int STAGE_BYTES = 2 * TILE_BYTES;       // 32768
static constexpr int SMEM_TOTAL  = STAGES * STAGE_BYTES; // 98304 -> 2 CTAs/SM

// --------------------------------------------------------------------------
// Static scratch: fp16 copies of A and B
// --------------------------------------------------------------------------
__device__ __half g_Ah[(size_t)M_TOTAL * K_DIM];
__device__ __half g_Bh[(size_t)N_TOTAL * K_DIM];

// --------------------------------------------------------------------------
// Merged convert kernel: A then B in one grid (fp32 -> fp16, 4-wide)
// --------------------------------------------------------------------------
static constexpr int NA4 = (M_TOTAL * K_DIM) / 4;   // 8388608
static constexpr int NB4 = (N_TOTAL * K_DIM) / 4;   // 1048576

__global__ void __launch_bounds__(256)
cvt_all_kernel(const float4* __restrict__ A, const float4* __restrict__ B,
               uint2* __restrict__ Ah, uint2* __restrict__ Bh) {
    int i = blockIdx.x * blockDim.x + threadIdx.x;
    const float4* src;
    uint2* dst;
    if (i < NA4) {
        src = A + i; dst = Ah + i;
    } else {
        i -= NA4;
        if (i >= NB4) return;
        src = B + i; dst = Bh + i;
    }
    float4 v = *src;
    __half2 lo = __floats2half2_rn(v.x, v.y);
    __half2 hi = __floats2half2_rn(v.z, v.w);
    *dst = make_uint2(*reinterpret_cast<uint32_t*>(&lo), *reinterpret_cast<uint32_t*>(&hi));
}

// --------------------------------------------------------------------------
// PTX helpers
// --------------------------------------------------------------------------
__device__ __forceinline__ void cp_async16(uint32_t saddr, const void* gptr) {
    asm volatile("cp.async.cg.shared.global [%0], [%1], 16;"
                 :: "r"(saddr), "l"(__cvta_generic_to_global(gptr)) : "memory");
}

#define CP_COMMIT() asm volatile("cp.async.commit_group;" ::: "memory")
#define CP_WAIT(N)  asm volatile("cp.async.wait_group %0;" :: "n"(N) : "memory")

#define LDSM_X4(R, addr)                                                     \
    asm volatile("ldmatrix.sync.aligned.m8n8.x4.shared.b16 {%0,%1,%2,%3}, [%4];" \
                 : "=r"((R)[0]), "=r"((R)[1]), "=r"((R)[2]), "=r"((R)[3])    \
                 : "r"(addr))

#define MMA_F16(C, A, B0, B1)                                                \
    asm volatile("mma.sync.aligned.m16n8k16.row.col.f32.f16.f16.f32 "        \
                 "{%0,%1,%2,%3}, {%4,%5,%6,%7}, {%8,%9}, {%0,%1,%2,%3};"     \
                 : "+f"((C)[0]), "+f"((C)[1]), "+f"((C)[2]), "+f"((C)[3])    \
                 : "r"((A)[0]), "r"((A)[1]), "r"((A)[2]), "r"((A)[3]),       \
                   "r"(B0), "r"(B1))

__device__ __forceinline__ uint32_t swz(int row, int col_bytes) {
    return (uint32_t)(row * 128 + (col_bytes ^ ((row & 7) * 16)));
}

// --------------------------------------------------------------------------
// GEMM: CTA 128x128x64, 8 warps of 32x64, 3-stage cp.async, 2 CTAs/SM.
// Inner loop software-pipelined: LDSM(ks+1) issued before MMAs(ks).
// --------------------------------------------------------------------------
__global__ void __launch_bounds__(256, 2)
gemm_f16_kernel(float* __restrict__ C) {
    extern __shared__ uint8_t smem[];
    const uint32_t sbase = (uint32_t)__cvta_generic_to_shared(smem);

    const int tid  = threadIdx.x;
    const int lane = tid & 31;
    const int wid  = tid >> 5;
    const int wm   = (wid & 3) * 32;
    const int wn   = (wid >> 2) * 64;

    const int m0 = (blockIdx.x >> 3) * BM;   // n-fastest: octet shares A in L2
    const int n0 = (blockIdx.x & 7) * BN;

    auto load_stage = [&](int s, int kt) {
        const uint32_t st = sbase + s * STAGE_BYTES;
        const int kbase = kt * BK;
        #pragma unroll
        for (int i = 0; i < 4; i++) {
            const int idx = tid + i * 256;
            const int row = idx >> 3;
            const int ch  = idx & 7;
            const uint32_t soff = swz(row, ch * 16);
            cp_async16(st +              soff, &g_Ah[(size_t)(m0 + row) * K_DIM + kbase + ch * 8]);
            cp_async16(st + TILE_BYTES + soff, &g_Bh[(size_t)(n0 + row) * K_DIM + kbase + ch * 8]);
        }
    };

    // ---- ldmatrix address components ----
    int a_row[2], a_xor[2];
    #pragma unroll
    for (int m = 0; m < 2; m++) {
        const int r = wm + m * 16 + (lane & 15);
        a_row[m] = r * 128;
        a_xor[m] = (r & 7) * 16;
    }
    const int a_colb = (lane >> 4) * 16;
    int b_row[4], b_xor[4];
    #pragma unroll
    for (int p = 0; p < 4; p++) {
        const int r = wn + p * 16 + (lane & 7) + ((lane >> 4) << 3);
        b_row[p] = r * 128;
        b_xor[p] = (r & 7) * 16;
    }
    const int b_colb = ((lane >> 3) & 1) * 16;

    auto lds_frags = [&](uint32_t st, int ks, uint32_t (&a)[2][4], uint32_t (&b)[4][4]) {
        const int kb = ks * 32;
        #pragma unroll
        for (int m = 0; m < 2; m++)
            LDSM_X4(a[m], st + a_row[m] + ((kb + a_colb) ^ a_xor[m]));
        #pragma unroll
        for (int p = 0; p < 4; p++)
            LDSM_X4(b[p], st + TILE_BYTES + b_row[p] + ((kb + b_colb) ^ b_xor[p]));
    };

    float acc[2][8][4];
    #pragma unroll
    for (int m = 0; m < 2; m++)
        #pragma unroll
        for (int n = 0; n < 8; n++)
            #pragma unroll
            for (int q = 0; q < 4; q++) acc[m][n][q] = 0.f;

    // ---- prologue: 2 stages in flight ----
    load_stage(0, 0); CP_COMMIT();
    load_stage(1, 1); CP_COMMIT();

    uint32_t af[2][2][4], bf[2][4][4];   // double-buffered fragments

    // ---- mainloop ----
    for (int kt = 0; kt < NK; kt++) {
        if (kt < NK - 1) { CP_WAIT(1); } else { CP_WAIT(0); }
        __syncthreads();   // stage kt ready; stage (kt+2)%3 consumed by all
        if (kt + 2 < NK) {
            load_stage((kt + 2) % STAGES, kt + 2);
            CP_COMMIT();
        }

        const uint32_t st = sbase + (kt % STAGES) * STAGE_BYTES;

        lds_frags(st, 0, af[0], bf[0]);            // preload ks=0
        #pragma unroll
        for (int ks = 0; ks < 4; ks++) {
            const int cur = ks & 1;
            if (ks < 3)
                lds_frags(st, ks + 1, af[cur ^ 1], bf[cur ^ 1]);  // prefetch next
            #pragma unroll
            for (int m = 0; m < 2; m++)
                #pragma unroll
                for (int p = 0; p < 4; p++)
                    #pragma unroll
                    for (int q = 0; q < 2; q++)
                        MMA_F16(acc[m][2 * p + q], af[cur][m],
                                bf[cur][p][2 * q], bf[cur][p][2 * q + 1]);
        }
    }

    // ---- epilogue: direct STG.64 ----
    #pragma unroll
    for (int m = 0; m < 2; m++) {
        const int r0 = m0 + wm + m * 16 + (lane >> 2);
        #pragma unroll
        for (int n = 0; n < 8; n++) {
            const int col = n0 + wn + n * 8 + (lane & 3) * 2;
            float2* q0 = reinterpret_cast<float2*>(&C[(size_t)r0 * N_TOTAL + col]);
            float2* q1 = reinterpret_cast<float2*>(&C[(size_t)(r0 + 8) * N_TOTAL + col]);
            *q0 = make_float2(acc[m][n][0], acc[m][n][1]);
            *q1 = make_float2(acc[m][n][2], acc[m][n][3]);
        }
    }
}

// --------------------------------------------------------------------------
// Launch
// --------------------------------------------------------------------------
extern "C" void kernel_launch(void* const* d_in, const int* in_sizes, int n_in,
                              void* d_out, int out_size) {
    const float* A = (const float*)d_in[0];   // [8192, 4096]
    const float* B = (const float*)d_in[1];   // [1024, 4096]
    float* C = (float*)d_out;                 // [8192, 1024]

    __half *aH, *bH;
    cudaGetSymbolAddress((void**)&aH, g_Ah);
    cudaGetSymbolAddress((void**)&bH, g_Bh);

    const int ncv = NA4 + NB4;
    cvt_all_kernel<<<(ncv + 255) / 256, 256>>>((const float4*)A, (const float4*)B,
                                               (uint2*)aH, (uint2*)bH);

    static bool attr_set = false;
    if (!attr_set) {
        cudaFuncSetAttribute(gemm_f16_kernel,
                             cudaFuncAttributeMaxDynamicSharedMemorySize, SMEM_TOTAL);
        attr_set = true;
    }
    const int grid = (M_TOTAL / BM) * (N_TOTAL / BN);   // 512
    gemm_f16_kernel<<<grid, 256, SMEM_TOTAL>>>(C);
}